// round 1
// baseline (speedup 1.0000x reference)
#include <cuda_runtime.h>
#include <cstddef>

// out[tok][kr*32+o] = (kr%2 == k/32) ? L[v*16 + kr/2] * R[(kr*32 + k%32)*32 + o] : 0
// where v = x[tok], k = v / 786.
// 64 MiB fp32 output, HBM-store-bound. One CTA per token, 256 threads x float4.

static __device__ __forceinline__ float4 f4_scale(float l, float4 r) {
    return make_float4(l * r.x, l * r.y, l * r.z, l * r.w);
}

__global__ void __launch_bounds__(256) monarch_embed_kernel(
    const int* __restrict__ x,
    const float* __restrict__ L,
    const float* __restrict__ R,
    float* __restrict__ out)
{
    const int tok = blockIdx.x;
    const int v   = __ldg(&x[tok]);        // broadcast within block (L1 hit)
    const int k   = v / 786;               // block index in L
    const int s   = k >> 5;                // parity selector (k / 32)
    const int c   = k & 31;                // row within R block (k % 32)

    const int tid = threadIdx.x;           // 0..255
    const int j0  = tid << 2;              // output element base (float4)
    const int kr  = j0 >> 5;               // 0..31
    const int o   = j0 & 31;               // 0,4,...,28

    float4 res;
    if ((kr & 1) == s) {
        const int   m  = kr >> 1;                           // 0..15
        const float l  = __ldg(&L[(size_t)v * 16 + m]);     // one 64B line per token
        const float4 r4 = *reinterpret_cast<const float4*>(
            &R[((size_t)(kr * 32 + c)) * 32 + o]);          // L2-resident (128 KB total)
        res = f4_scale(l, r4);
    } else {
        res = make_float4(0.f, 0.f, 0.f, 0.f);
    }

    *reinterpret_cast<float4*>(&out[(size_t)tok * 1024 + j0]) = res;
}

extern "C" void kernel_launch(void* const* d_in, const int* in_sizes, int n_in,
                              void* d_out, int out_size) {
    const int*   x = (const int*)  d_in[0];   // (8, 2048) int32
    const float* L = (const float*)d_in[1];   // (64, 786, 16) f32
    const float* R = (const float*)d_in[2];   // (32, 32, 32) f32
    // d_in[3] = p : analytically folded in (perfect_shuffle(64, 1024))

    const int ntok = out_size / 1024;         // 16384 tokens, 1024 f32 each
    monarch_embed_kernel<<<ntok, 256>>>(x, L, R, (float*)d_out);
}

// round 2
// speedup vs baseline: 1.1711x; 1.1711x over previous
#include <cuda_runtime.h>
#include <cstddef>

// Monarch embedding, analytically folded:
//   out[tok][kr*32+o] = (kr&1 == s) ? L[v*16 + kr/2] * R[(kr*32 + c)*32 + o] : 0
//   v = x[tok], k = v/786, s = k>>5, c = k&31.
//
// Output (64 MiB) is L2-resident -> latency/issue bound, NOT HBM bound.
// Layout: 4 tokens per CTA (MLP=4). 8 warps; warps 0-3 own parity-0 kr rows,
// warps 4-7 parity-1. A warp is all-compute or all-zero per token -> no
// divergence, zero-warps issue no loads.
//
// Warp w: p = w>>2 (parity), q = w&3. Lane l: r = l>>3, o = (l&7)*4.
//   i = 4q + r (0..15), kr = 2i + p. L addr = L[v*16 + i] (4 consecutive
//   floats per warp -> 1 sector). Store: lane float4 at out[tok][kr*32+o];
//   per warp 4 fully-covered 128B lines.

__global__ void __launch_bounds__(256) monarch_embed_kernel(
    const int* __restrict__ x,
    const float* __restrict__ L,
    const float* __restrict__ R,
    float* __restrict__ out)
{
    const int tb  = blockIdx.x << 2;       // 4 tokens per CTA
    const int tid = threadIdx.x;
    const int w   = tid >> 5;
    const int l   = tid & 31;
    const int p   = w >> 2;                // warp parity (0/1)
    const int q   = w & 3;
    const int r   = l >> 3;
    const int o   = (l & 7) << 2;
    const int i   = (q << 2) + r;          // 0..15 : L column / row pair index
    const int kr  = (i << 1) + p;          // 0..31 : output row

    // One aligned 128-bit load covers x for all 4 tokens (tb % 4 == 0).
    const int4 xv = *reinterpret_cast<const int4*>(x + tb);
    int vs[4] = {xv.x, xv.y, xv.z, xv.w};

    float4 res[4];

#pragma unroll
    for (int t = 0; t < 4; t++) {
        const int v = vs[t];
        const int k = v / 786;             // strength-reduced by compiler
        const int s = k >> 5;
        const int c = k & 31;

        float4 acc = make_float4(0.f, 0.f, 0.f, 0.f);
        if (s == p) {                      // warp-uniform: no divergence
            const float  lv = __ldg(&L[(size_t)v * 16 + i]);
            const float4 r4 = *reinterpret_cast<const float4*>(
                &R[((size_t)((kr << 5) + c) << 5) + o]);
            acc = make_float4(lv * r4.x, lv * r4.y, lv * r4.z, lv * r4.w);
        }
        res[t] = acc;
    }

#pragma unroll
    for (int t = 0; t < 4; t++) {
        *reinterpret_cast<float4*>(
            &out[(size_t)(tb + t) * 1024 + (kr << 5) + o]) = res[t];
    }
}

extern "C" void kernel_launch(void* const* d_in, const int* in_sizes, int n_in,
                              void* d_out, int out_size) {
    const int*   x = (const int*)  d_in[0];   // (8, 2048) int32
    const float* L = (const float*)d_in[1];   // (64, 786, 16) f32
    const float* R = (const float*)d_in[2];   // (32, 32, 32) f32
    // d_in[3] = p : analytically folded (perfect_shuffle(64, 1024))

    const int ntok = out_size / 1024;         // 16384 tokens
    monarch_embed_kernel<<<ntok / 4, 256>>>(x, L, R, (float*)d_out);
}